// round 2
// baseline (speedup 1.0000x reference)
#include <cuda_runtime.h>
#include <math.h>

// Problem: q,k,v are [B=2, H=16, C=128, L=2048], L contiguous (fp32).
// logits = q^T k ; weights = softmax over the *q* axis ; out = v @ weights^T.
//
//   r[k]   = sum_q exp(S[q,k])                (column sums over q)
//   O[c,q] = sum_k (V[c,k] / r[k]) * exp(S[q,k])
#define BH   32
#define CDIM 128
#define LQ   2048
#define LKV  2048

// Scratch (device globals: allocation is banned).
// g_E : exp(S) per bh, layout [bh][q][k], k contiguous.  512 MB.
// g_r : per-(bh,k) column sums over q; inverted in place by rinv_kernel.
__device__ float g_E[(size_t)BH * LQ * LKV];
__device__ float g_r[BH * LKV];

// ---------------------------------------------------------------------------
// Kernel 0: zero the column-sum accumulator (re-zeroed every replay).
// ---------------------------------------------------------------------------
__global__ void zero_r_kernel() {
    int i = blockIdx.x * blockDim.x + threadIdx.x;
    if (i < BH * LKV) g_r[i] = 0.0f;
}

// ---------------------------------------------------------------------------
// Kernel 1: S = Q^T K (reduction over c=128), fused exp epilogue.
//   Writes E[q][k] = exp(S[q][k]) and accumulates column sums (over q,
//   per k) into g_r. No max-subtraction needed: |S| <~ 70 and column sums
//   stay far below fp32 overflow (e^70 ~ 2.5e30, sums < 1e34).
// Tile: 128(q) x 128(k), TK = 16 over c, double-buffered smem.
// Block 256 threads, 8x8 microtile. grid = (LQ/128, LKV/128, BH)
// ---------------------------------------------------------------------------
__global__ __launch_bounds__(256) void gemm1_exp_kernel(
    const float* __restrict__ Q, const float* __restrict__ K)
{
    __shared__ float Qs[2][16][128];
    __shared__ float Ks[2][16][128];
    __shared__ float cs[128];

    const int bh = blockIdx.z;
    const int q0 = blockIdx.x * 128;
    const int k0 = blockIdx.y * 128;
    const float* Qb = Q + (size_t)bh * CDIM * LQ;
    const float* Kb = K + (size_t)bh * CDIM * LKV;

    const int tid = threadIdx.x;
    const int tx  = tid & 15;        // k-fragment selector
    const int ty  = tid >> 4;        // q-fragment selector

    // loader mapping: 16x128 tile = 2048 floats = 256 threads * 2 float4
    const int lq = (tid & 31) * 4;   // float4 column 0..124
    const int lc = tid >> 5;         // row base 0..7 (rows lc, lc+8)

    float acc[8][8];
#pragma unroll
    for (int i = 0; i < 8; i++)
#pragma unroll
        for (int j = 0; j < 8; j++) acc[i][j] = 0.0f;

    float4 pq[2], pk[2];
    // prefetch stage 0
#pragma unroll
    for (int m = 0; m < 2; m++) {
        int cc = lc + m * 8;
        pq[m] = *(const float4*)&Qb[(size_t)cc * LQ  + q0 + lq];
        pk[m] = *(const float4*)&Kb[(size_t)cc * LKV + k0 + lq];
    }
#pragma unroll
    for (int m = 0; m < 2; m++) {
        int cc = lc + m * 8;
        *(float4*)&Qs[0][cc][lq] = pq[m];
        *(float4*)&Ks[0][cc][lq] = pk[m];
    }
    __syncthreads();

#pragma unroll 1
    for (int s = 0; s < 8; s++) {
        const int buf = s & 1;
        if (s < 7) {                 // issue next-stage LDGs early
            int c0 = (s + 1) * 16;
#pragma unroll
            for (int m = 0; m < 2; m++) {
                int cc = c0 + lc + m * 8;
                pq[m] = *(const float4*)&Qb[(size_t)cc * LQ  + q0 + lq];
                pk[m] = *(const float4*)&Kb[(size_t)cc * LKV + k0 + lq];
            }
        }
#pragma unroll
        for (int cc = 0; cc < 16; cc++) {
            float4 a0 = *(const float4*)&Qs[buf][cc][ty * 4];
            float4 a1 = *(const float4*)&Qs[buf][cc][64 + ty * 4];
            float4 b0 = *(const float4*)&Ks[buf][cc][tx * 4];
            float4 b1 = *(const float4*)&Ks[buf][cc][64 + tx * 4];
            float a[8] = {a0.x, a0.y, a0.z, a0.w, a1.x, a1.y, a1.z, a1.w};
            float b[8] = {b0.x, b0.y, b0.z, b0.w, b1.x, b1.y, b1.z, b1.w};
#pragma unroll
            for (int i = 0; i < 8; i++)
#pragma unroll
                for (int j = 0; j < 8; j++)
                    acc[i][j] = fmaf(a[i], b[j], acc[i][j]);
        }
        if (s < 7) {
#pragma unroll
            for (int m = 0; m < 2; m++) {
                int cc = lc + m * 8;
                *(float4*)&Qs[buf ^ 1][cc][lq] = pq[m];
                *(float4*)&Ks[buf ^ 1][cc][lq] = pk[m];
            }
        }
        __syncthreads();
    }

    // ---- epilogue: exp, store E, accumulate column sums ----
    if (tid < 128) cs[tid] = 0.0f;
    __syncthreads();

    float colp[8];
#pragma unroll
    for (int j = 0; j < 8; j++) colp[j] = 0.0f;

    float* Eb = g_E + (size_t)bh * LQ * LKV;
#pragma unroll
    for (int i = 0; i < 8; i++) {
        int qr = q0 + ty * 4 + (i & 3) + (i >> 2) * 64;
        float ev[8];
#pragma unroll
        for (int j = 0; j < 8; j++) {
            ev[j] = expf(acc[i][j]);
            colp[j] += ev[j];
        }
        *(float4*)&Eb[(size_t)qr * LKV + k0 + tx * 4] =
            make_float4(ev[0], ev[1], ev[2], ev[3]);
        *(float4*)&Eb[(size_t)qr * LKV + k0 + 64 + tx * 4] =
            make_float4(ev[4], ev[5], ev[6], ev[7]);
    }
#pragma unroll
    for (int j = 0; j < 8; j++) {
        int kc = tx * 4 + (j & 3) + (j >> 2) * 64;
        atomicAdd(&cs[kc], colp[j]);
    }
    __syncthreads();
    if (tid < 128) atomicAdd(&g_r[bh * LKV + k0 + tid], cs[tid]);
}

// ---------------------------------------------------------------------------
// Kernel 2: invert column sums in place: r <- 1/r
// ---------------------------------------------------------------------------
__global__ void rinv_kernel() {
    int i = blockIdx.x * blockDim.x + threadIdx.x;
    if (i < BH * LKV) g_r[i] = 1.0f / g_r[i];
}

// ---------------------------------------------------------------------------
// Kernel 3: O[c][q] = sum_k (V[c][k] * rinv[k]) * E[q][k]
// NT-style GEMM: M=c=128, N=q (tiled 128), K=k=2048 (TK=16),
// double-buffered, float4 gmem loads, rinv folded into the V operand.
// grid = (LQ/128, BH)
// ---------------------------------------------------------------------------
__global__ __launch_bounds__(256) void gemm2_kernel(
    const float* __restrict__ V, float* __restrict__ Out)
{
    __shared__ float As[2][16][132];  // [kk][c]  (transposed at load, padded)
    __shared__ float Bs[2][16][132];  // [kk][q]

    const int bh = blockIdx.y;
    const int q0 = blockIdx.x * 128;
    const float* Vb = V   + (size_t)bh * CDIM * LKV;
    const float* Eb = g_E + (size_t)bh * LQ * LKV;
    const float* rb = g_r + bh * LKV;

    const int tid = threadIdx.x;
    const int tx  = tid & 15;   // q-fragment
    const int ty  = tid >> 4;   // c-fragment

    float acc[8][8];
#pragma unroll
    for (int i = 0; i < 8; i++)
#pragma unroll
        for (int j = 0; j < 8; j++) acc[i][j] = 0.0f;

    // loader mapping: 512 float4 per (As,Bs) stage, 256 threads * 2 iters
    //   idx = tid + 256*it ; row = idx>>2 (0..127) ; g = idx&3 (k-group)
    float4 pv[2], pe[2], pr[2];

#pragma unroll
    for (int it = 0; it < 2; it++) {
        int idx = tid + 256 * it, row = idx >> 2, g = idx & 3;
        pv[it] = *(const float4*)&Vb[(size_t)row * LKV + g * 4];
        pe[it] = *(const float4*)&Eb[(size_t)(q0 + row) * LKV + g * 4];
        pr[it] = *(const float4*)&rb[g * 4];
    }
#pragma unroll
    for (int it = 0; it < 2; it++) {
        int idx = tid + 256 * it, row = idx >> 2, g = idx & 3;
        As[0][g * 4 + 0][row] = pv[it].x * pr[it].x;
        As[0][g * 4 + 1][row] = pv[it].y * pr[it].y;
        As[0][g * 4 + 2][row] = pv[it].z * pr[it].z;
        As[0][g * 4 + 3][row] = pv[it].w * pr[it].w;
        Bs[0][g * 4 + 0][row] = pe[it].x;
        Bs[0][g * 4 + 1][row] = pe[it].y;
        Bs[0][g * 4 + 2][row] = pe[it].z;
        Bs[0][g * 4 + 3][row] = pe[it].w;
    }
    __syncthreads();

#pragma unroll 1
    for (int s = 0; s < LKV / 16; s++) {
        const int buf = s & 1;
        if (s < LKV / 16 - 1) {
            int k0 = (s + 1) * 16;
#pragma unroll
            for (int it = 0; it < 2; it++) {
                int idx = tid + 256 * it, row = idx >> 2, g = idx & 3;
                pv[it] = *(const float4*)&Vb[(size_t)row * LKV + k0 + g * 4];
                pe[it] = *(const float4*)&Eb[(size_t)(q0 + row) * LKV + k0 + g * 4];
                pr[it] = *(const float4*)&rb[k0 + g * 4];
            }
        }
#pragma unroll
        for (int kk = 0; kk < 16; kk++) {
            float4 a0 = *(const float4*)&As[buf][kk][ty * 4];
            float4 a1 = *(const float4*)&As[buf][kk][64 + ty * 4];
            float4 b0 = *(const float4*)&Bs[buf][kk][tx * 4];
            float4 b1 = *(const float4*)&Bs[buf][kk][64 + tx * 4];
            float a[8] = {a0.x, a0.y, a0.z, a0.w, a1.x, a1.y, a1.z, a1.w};
            float b[8] = {b0.x, b0.y, b0.z, b0.w, b1.x, b1.y, b1.z, b1.w};
#pragma unroll
            for (int i = 0; i < 8; i++)
#pragma unroll
                for (int j = 0; j < 8; j++)
                    acc[i][j] = fmaf(a[i], b[j], acc[i][j]);
        }
        if (s < LKV / 16 - 1) {
#pragma unroll
            for (int it = 0; it < 2; it++) {
                int idx = tid + 256 * it, row = idx >> 2, g = idx & 3;
                As[buf ^ 1][g * 4 + 0][row] = pv[it].x * pr[it].x;
                As[buf ^ 1][g * 4 + 1][row] = pv[it].y * pr[it].y;
                As[buf ^ 1][g * 4 + 2][row] = pv[it].z * pr[it].z;
                As[buf ^ 1][g * 4 + 3][row] = pv[it].w * pr[it].w;
                Bs[buf ^ 1][g * 4 + 0][row] = pe[it].x;
                Bs[buf ^ 1][g * 4 + 1][row] = pe[it].y;
                Bs[buf ^ 1][g * 4 + 2][row] = pe[it].z;
                Bs[buf ^ 1][g * 4 + 3][row] = pe[it].w;
            }
        }
        __syncthreads();
    }

    // Out layout: [bh][c][q], q contiguous
#pragma unroll
    for (int i = 0; i < 8; i++) {
        int crow = ty * 4 + (i & 3) + (i >> 2) * 64;
        float* ob = Out + ((size_t)bh * CDIM + crow) * LQ + q0;
        *(float4*)&ob[tx * 4] =
            make_float4(acc[i][0], acc[i][1], acc[i][2], acc[i][3]);
        *(float4*)&ob[64 + tx * 4] =
            make_float4(acc[i][4], acc[i][5], acc[i][6], acc[i][7]);
    }
}

// ---------------------------------------------------------------------------
extern "C" void kernel_launch(void* const* d_in, const int* in_sizes, int n_in,
                              void* d_out, int out_size)
{
    const float* q = (const float*)d_in[0];
    const float* k = (const float*)d_in[1];
    const float* v = (const float*)d_in[2];
    float* out = (float*)d_out;

    zero_r_kernel<<<(BH * LKV + 255) / 256, 256>>>();

    dim3 g1(LQ / 128, LKV / 128, BH);
    gemm1_exp_kernel<<<g1, 256>>>(q, k);

    rinv_kernel<<<(BH * LKV + 255) / 256, 256>>>();

    dim3 g2(LQ / 128, BH);
    gemm2_kernel<<<g2, 256>>>(v, out);
}

// round 4
// speedup vs baseline: 2.0611x; 2.0611x over previous
#include <cuda_runtime.h>
#include <cuda_bf16.h>
#include <cstdint>

// Problem: q,k,v [B=2,H=16,C=128,L=2048] fp32, L contiguous.
// weights = softmax over the q axis:
//   r[k]   = sum_q exp(S[q,k]),  S = Q^T K
//   O[c,q] = sum_k (V[c,k]/r[k]) * exp(S[q,k])
// Engine: mma.sync.m16n8k16 bf16 (sm_80+ ISA; tcgen05 is unavailable at the
// harness's compute_100 PTX target). Precision via hi/lo bf16 split, 3-pass.
#define BH 32
#define CD 128
#define LL 2048

// ---------------- scratch (device globals; allocation is banned) ----------
__device__ __nv_bfloat16 g_Qh[(size_t)BH * LL * CD];  // [bh][q][c]
__device__ __nv_bfloat16 g_Ql[(size_t)BH * LL * CD];
__device__ __nv_bfloat16 g_Kh[(size_t)BH * LL * CD];  // [bh][k][c]
__device__ __nv_bfloat16 g_Kl[(size_t)BH * LL * CD];
__device__ __nv_bfloat16 g_Vh[(size_t)BH * CD * LL];  // [bh][c][k] (V*rinv)
__device__ __nv_bfloat16 g_Vl[(size_t)BH * CD * LL];
__device__ __nv_bfloat16 g_Eh[(size_t)BH * LL * LL];  // [bh][q][k]
__device__ __nv_bfloat16 g_El[(size_t)BH * LL * LL];
__device__ float         g_r[BH * LL];

// ---------------- smem geometry -------------------------------------------
#define TSTR   144                // bytes/row in 64-col bf16 tiles (odd 16B)
#define TILE_B (128 * TSTR)       // 18432
#define BUF_B  (4 * TILE_B)       // 73728 : Ah | Al | Bh | Bl
#define OFF_AH 0
#define OFF_AL TILE_B
#define OFF_BH (2 * TILE_B)
#define OFF_BL (3 * TILE_B)
#define OFF_CS (2 * BUF_B)        // 147456
#define SMEM_SZ (OFF_CS + 512)
#define ESTR   272                // staging row stride (68 u32, odd 16B)

// ---------------- ptx helpers ---------------------------------------------
__device__ __forceinline__ uint32_t smem_u32(const void* p) {
    uint32_t a;
    asm("{ .reg .u64 t; cvta.to.shared.u64 t, %1; cvt.u32.u64 %0, t; }"
        : "=r"(a) : "l"(p));
    return a;
}
__device__ __forceinline__ void cpa(uint32_t d, const void* s) {
    asm volatile("cp.async.cg.shared.global [%0], [%1], 16;"
                 :: "r"(d), "l"(__cvta_generic_to_global(s)));
}
#define CP_COMMIT() asm volatile("cp.async.commit_group;" ::: "memory")
#define CP_WAIT(n)  asm volatile("cp.async.wait_group %0;" :: "n"(n) : "memory")

__device__ __forceinline__ void ldsm4(uint32_t* r, uint32_t a) {
    asm volatile("ldmatrix.sync.aligned.m8n8.x4.shared.b16 {%0,%1,%2,%3}, [%4];"
                 : "=r"(r[0]), "=r"(r[1]), "=r"(r[2]), "=r"(r[3]) : "r"(a));
}
__device__ __forceinline__ void ldsm2(uint32_t* r, uint32_t a) {
    asm volatile("ldmatrix.sync.aligned.m8n8.x2.shared.b16 {%0,%1}, [%2];"
                 : "=r"(r[0]), "=r"(r[1]) : "r"(a));
}
__device__ __forceinline__ void mma16816(float* d, const uint32_t* a, const uint32_t* b) {
    asm volatile("mma.sync.aligned.m16n8k16.row.col.f32.bf16.bf16.f32 "
                 "{%0,%1,%2,%3}, {%4,%5,%6,%7}, {%8,%9}, {%0,%1,%2,%3};"
                 : "+f"(d[0]), "+f"(d[1]), "+f"(d[2]), "+f"(d[3])
                 : "r"(a[0]), "r"(a[1]), "r"(a[2]), "r"(a[3]),
                   "r"(b[0]), "r"(b[1]));
}

// load one 4-tile k-chunk (Ah,Al,Bh,Bl: 128 rows x 64 bf16 each) via cp.async
__device__ __forceinline__ void load_chunk(
    uint32_t buf, const __nv_bfloat16* ah, const __nv_bfloat16* al,
    const __nv_bfloat16* bh, const __nv_bfloat16* bl,
    int strideA, int strideB, int tid)
{
#pragma unroll
    for (int r = 0; r < 4; r++) {
        int idx = tid + 256 * r;       // 0..1023
        int row = idx >> 3, seg = idx & 7;
        uint32_t d = buf + row * TSTR + seg * 16;
        size_t sa = (size_t)row * strideA + seg * 8;
        size_t sb = (size_t)row * strideB + seg * 8;
        cpa(d + OFF_AH, ah + sa);
        cpa(d + OFF_AL, al + sa);
        cpa(d + OFF_BH, bh + sb);
        cpa(d + OFF_BL, bl + sb);
    }
}

// one 64-deep k-chunk of 3-pass split mma: acc += Ah*Bh + Ah*Bl + Al*Bh
__device__ __forceinline__ void mma_chunk(
    float acc[4][4][4], uint32_t buf, int wm, int wn, int lane)
{
    uint32_t a_base = buf + (uint32_t)(wm * 64 + (lane & 15)) * TSTR + ((lane >> 4) << 4);
    uint32_t b_base = buf + (uint32_t)(wn * 32 + (lane & 7)) * TSTR + (((lane >> 3) & 1) << 4);
#pragma unroll
    for (int ks = 0; ks < 4; ks++) {
        uint32_t ah[4][4], al[4][4], bhf[4][2], blf[4][2];
#pragma unroll
        for (int i = 0; i < 4; i++) {
            ldsm4(ah[i], a_base + OFF_AH + i * 16 * TSTR + ks * 32);
            ldsm4(al[i], a_base + OFF_AL + i * 16 * TSTR + ks * 32);
        }
#pragma unroll
        for (int j = 0; j < 4; j++) {
            ldsm2(bhf[j], b_base + OFF_BH + j * 8 * TSTR + ks * 32);
            ldsm2(blf[j], b_base + OFF_BL + j * 8 * TSTR + ks * 32);
        }
#pragma unroll
        for (int i = 0; i < 4; i++)
#pragma unroll
            for (int j = 0; j < 4; j++) {
                mma16816(acc[i][j], ah[i], bhf[j]);
                mma16816(acc[i][j], ah[i], blf[j]);
                mma16816(acc[i][j], al[i], bhf[j]);
            }
    }
}

// ---------------------------------------------------------------------------
// small kernels
// ---------------------------------------------------------------------------
__global__ void zero_r_kernel() {
    int i = blockIdx.x * blockDim.x + threadIdx.x;
    if (i < BH * LL) g_r[i] = 0.0f;
}
__global__ void rinv_kernel() {
    int i = blockIdx.x * blockDim.x + threadIdx.x;
    if (i < BH * LL) g_r[i] = 1.0f / g_r[i];
}

// transpose+split: X [bh][c][l] f32 -> (Xh,Xl) [bh][l][c] bf16. sel 0=Q 1=K
__global__ void splitT_kernel(const float* __restrict__ X, int sel) {
    __shared__ float tbuf[32][33];
    int bh = blockIdx.z, c0 = blockIdx.y * 32, l0 = blockIdx.x * 32;
    int tx = threadIdx.x, ty = threadIdx.y;
    const float* Xb = X + ((size_t)bh * CD + c0) * LL + l0;
#pragma unroll
    for (int i = 0; i < 4; i++)
        tbuf[ty + 8 * i][tx] = Xb[(size_t)(ty + 8 * i) * LL + tx];
    __syncthreads();
    __nv_bfloat16* Dh = (sel ? g_Kh : g_Qh) + ((size_t)bh * LL + l0) * CD + c0;
    __nv_bfloat16* Dl = (sel ? g_Kl : g_Ql) + ((size_t)bh * LL + l0) * CD + c0;
#pragma unroll
    for (int i = 0; i < 4; i++) {
        float v = tbuf[tx][ty + 8 * i];
        __nv_bfloat16 h = __float2bfloat16(v);
        Dh[(size_t)(ty + 8 * i) * CD + tx] = h;
        Dl[(size_t)(ty + 8 * i) * CD + tx] = __float2bfloat16(v - __bfloat162float(h));
    }
}

// Vr = V * rinv -> bf16 hi/lo, layout unchanged [bh][c][k]
__global__ void vprep_kernel(const float* __restrict__ V) {
    const size_t N = (size_t)BH * CD * LL;
    for (size_t i = (size_t)blockIdx.x * blockDim.x + threadIdx.x; i < N;
         i += (size_t)gridDim.x * blockDim.x) {
        int k = (int)(i & (LL - 1));
        int bh = (int)(i / ((size_t)CD * LL));
        float v = V[i] * g_r[bh * LL + k];
        __nv_bfloat16 h = __float2bfloat16(v);
        g_Vh[i] = h;
        g_Vl[i] = __float2bfloat16(v - __bfloat162float(h));
    }
}

// ---------------------------------------------------------------------------
// GEMM1: S tile [128q x 128k] over c=128 (2 chunks), exp epilogue,
//        colsum->g_r, split-store Eh/El via coalescing staging.
// grid (16 qt, 16 kt, 32 bh), 256 threads
// ---------------------------------------------------------------------------
__global__ __launch_bounds__(256) void gemm1_kernel() {
    extern __shared__ char sm[];
    const uint32_t sb = smem_u32(sm);
    const int tid = threadIdx.x, wid = tid >> 5, lane = tid & 31;
    const int wm = wid & 1, wn = wid >> 1;
    const int q0 = blockIdx.x * 128, k0 = blockIdx.y * 128, bh = blockIdx.z;

    float* cs = (float*)(sm + OFF_CS);
    if (tid < 128) cs[tid] = 0.0f;

    const __nv_bfloat16* Qh = g_Qh + ((size_t)bh * LL + q0) * CD;
    const __nv_bfloat16* Ql = g_Ql + ((size_t)bh * LL + q0) * CD;
    const __nv_bfloat16* Kh = g_Kh + ((size_t)bh * LL + k0) * CD;
    const __nv_bfloat16* Kl = g_Kl + ((size_t)bh * LL + k0) * CD;

    load_chunk(sb, Qh, Ql, Kh, Kl, CD, CD, tid);
    CP_COMMIT();
    load_chunk(sb + BUF_B, Qh + 64, Ql + 64, Kh + 64, Kl + 64, CD, CD, tid);
    CP_COMMIT();

    float acc[4][4][4];
#pragma unroll
    for (int i = 0; i < 4; i++)
#pragma unroll
        for (int j = 0; j < 4; j++)
#pragma unroll
            for (int v = 0; v < 4; v++) acc[i][j][v] = 0.0f;

    CP_WAIT(1);
    __syncthreads();
    mma_chunk(acc, sb, wm, wn, lane);
    CP_WAIT(0);
    __syncthreads();
    mma_chunk(acc, sb + BUF_B, wm, wn, lane);
    __syncthreads();   // all warps done with buffers -> staging may reuse

    // exp in place + column sums
#pragma unroll
    for (int i = 0; i < 4; i++)
#pragma unroll
        for (int j = 0; j < 4; j++)
#pragma unroll
            for (int v = 0; v < 4; v++) acc[i][j][v] = __expf(acc[i][j][v]);

#pragma unroll
    for (int j = 0; j < 4; j++) {
        float p0 = 0.0f, p1 = 0.0f;
#pragma unroll
        for (int i = 0; i < 4; i++) {
            p0 += acc[i][j][0] + acc[i][j][2];
            p1 += acc[i][j][1] + acc[i][j][3];
        }
        p0 += __shfl_xor_sync(0xffffffffu, p0, 4);
        p1 += __shfl_xor_sync(0xffffffffu, p1, 4);
        p0 += __shfl_xor_sync(0xffffffffu, p0, 8);
        p1 += __shfl_xor_sync(0xffffffffu, p1, 8);
        p0 += __shfl_xor_sync(0xffffffffu, p0, 16);
        p1 += __shfl_xor_sync(0xffffffffu, p1, 16);
        if ((lane >> 2) == 0) {
            int c = wn * 32 + j * 8 + (lane & 3) * 2;
            atomicAdd(&cs[c], p0);
            atomicAdd(&cs[c + 1], p1);
        }
    }

    // stage hi/lo bf16x2 tiles (conflict-free 272B-row layout)
    uint32_t* stH = (uint32_t*)(sm);
    uint32_t* stL = (uint32_t*)(sm + 128 * ESTR);
#pragma unroll
    for (int i = 0; i < 4; i++)
#pragma unroll
        for (int j = 0; j < 4; j++) {
            int r  = wm * 64 + i * 16 + (lane >> 2);
            int cu = wn * 16 + j * 4 + (lane & 3);
            float a0 = acc[i][j][0], a1 = acc[i][j][1];
            float a2 = acc[i][j][2], a3 = acc[i][j][3];
            __nv_bfloat16 h0 = __float2bfloat16(a0), h1 = __float2bfloat16(a1);
            __nv_bfloat16 h2 = __float2bfloat16(a2), h3 = __float2bfloat16(a3);
            stH[r * 68 + cu] = (uint32_t)__bfloat16_as_ushort(h0) |
                               ((uint32_t)__bfloat16_as_ushort(h1) << 16);
            stH[(r + 8) * 68 + cu] = (uint32_t)__bfloat16_as_ushort(h2) |
                                     ((uint32_t)__bfloat16_as_ushort(h3) << 16);
            __nv_bfloat16 l0 = __float2bfloat16(a0 - __bfloat162float(h0));
            __nv_bfloat16 l1 = __float2bfloat16(a1 - __bfloat162float(h1));
            __nv_bfloat16 l2 = __float2bfloat16(a2 - __bfloat162float(h2));
            __nv_bfloat16 l3 = __float2bfloat16(a3 - __bfloat162float(h3));
            stL[r * 68 + cu] = (uint32_t)__bfloat16_as_ushort(l0) |
                               ((uint32_t)__bfloat16_as_ushort(l1) << 16);
            stL[(r + 8) * 68 + cu] = (uint32_t)__bfloat16_as_ushort(l2) |
                                     ((uint32_t)__bfloat16_as_ushort(l3) << 16);
        }
    __syncthreads();

    if (tid < 128) atomicAdd(&g_r[bh * LL + k0 + tid], cs[tid]);

    __nv_bfloat16* EhD = g_Eh + ((size_t)bh * LL + q0) * LL + k0;
    __nv_bfloat16* ElD = g_El + ((size_t)bh * LL + q0) * LL + k0;
#pragma unroll
    for (int r8 = 0; r8 < 8; r8++) {
        int idx = tid + 256 * r8;        // 0..2047
        int row = idx >> 4, seg = idx & 15;
        *(uint4*)(EhD + (size_t)row * LL + seg * 8) =
            *(const uint4*)((const char*)sm + row * ESTR + seg * 16);
        *(uint4*)(ElD + (size_t)row * LL + seg * 8) =
            *(const uint4*)((const char*)sm + 128 * ESTR + row * ESTR + seg * 16);
    }
}

// ---------------------------------------------------------------------------
// GEMM2: O[c,q] = sum_k Vr[c,k]*E[q,k]; 32 double-buffered k-chunks.
// grid (16 qt, 32 bh), 256 threads
// ---------------------------------------------------------------------------
__global__ __launch_bounds__(256) void gemm2_kernel(float* __restrict__ Out) {
    extern __shared__ char sm[];
    const uint32_t sb = smem_u32(sm);
    const int tid = threadIdx.x, wid = tid >> 5, lane = tid & 31;
    const int wm = wid & 1, wn = wid >> 1;
    const int q0 = blockIdx.x * 128, bh = blockIdx.y;

    const __nv_bfloat16* Vh = g_Vh + (size_t)bh * CD * LL;
    const __nv_bfloat16* Vl = g_Vl + (size_t)bh * CD * LL;
    const __nv_bfloat16* Eh = g_Eh + ((size_t)bh * LL + q0) * LL;
    const __nv_bfloat16* El = g_El + ((size_t)bh * LL + q0) * LL;

    load_chunk(sb, Vh, Vl, Eh, El, LL, LL, tid);
    CP_COMMIT();

    float acc[4][4][4];
#pragma unroll
    for (int i = 0; i < 4; i++)
#pragma unroll
        for (int j = 0; j < 4; j++)
#pragma unroll
            for (int v = 0; v < 4; v++) acc[i][j][v] = 0.0f;

#pragma unroll 1
    for (int ck = 0; ck < 32; ck++) {
        if (ck < 31) {
            int off = (ck + 1) * 64;
            load_chunk(sb + ((ck + 1) & 1) * BUF_B, Vh + off, Vl + off,
                       Eh + off, El + off, LL, LL, tid);
            CP_COMMIT();
            CP_WAIT(1);
        } else {
            CP_WAIT(0);
        }
        __syncthreads();
        mma_chunk(acc, sb + (ck & 1) * BUF_B, wm, wn, lane);
        __syncthreads();
    }

    // epilogue: direct f32 stores, Out [bh][c][q]
#pragma unroll
    for (int i = 0; i < 4; i++)
#pragma unroll
        for (int j = 0; j < 4; j++) {
            int r  = wm * 64 + i * 16 + (lane >> 2);
            int qc = q0 + wn * 32 + j * 8 + (lane & 3) * 2;
            float* ob = Out + ((size_t)bh * CD + r) * LL + qc;
            *(float2*)ob = make_float2(acc[i][j][0], acc[i][j][1]);
            *(float2*)(ob + 8 * LL) = make_float2(acc[i][j][2], acc[i][j][3]);
        }
}

// ---------------------------------------------------------------------------
extern "C" void kernel_launch(void* const* d_in, const int* in_sizes, int n_in,
                              void* d_out, int out_size)
{
    const float* q = (const float*)d_in[0];
    const float* k = (const float*)d_in[1];
    const float* v = (const float*)d_in[2];
    float* out = (float*)d_out;

    cudaFuncSetAttribute(gemm1_kernel, cudaFuncAttributeMaxDynamicSharedMemorySize, SMEM_SZ);
    cudaFuncSetAttribute(gemm2_kernel, cudaFuncAttributeMaxDynamicSharedMemorySize, SMEM_SZ);

    zero_r_kernel<<<BH * LL / 256, 256>>>();
    splitT_kernel<<<dim3(LL / 32, CD / 32, BH), dim3(32, 8)>>>(q, 0);
    splitT_kernel<<<dim3(LL / 32, CD / 32, BH), dim3(32, 8)>>>(k, 1);
    gemm1_kernel<<<dim3(16, 16, BH), 256, SMEM_SZ>>>();
    rinv_kernel<<<BH * LL / 256, 256>>>();
    vprep_kernel<<<4096, 256>>>(v);
    gemm2_kernel<<<dim3(16, BH), 256, SMEM_SZ>>>(out);
}

// round 5
// speedup vs baseline: 2.2821x; 1.1072x over previous
#include <cuda_runtime.h>
#include <cuda_bf16.h>
#include <cstdint>

// Problem: q,k,v [B=2,H=16,C=128,L=2048] fp32, L contiguous.
// weights = softmax over the q axis:
//   r[k]   = sum_q exp(S[q,k]),  S = Q^T K
//   O[c,q] = sum_k (V[c,k]/r[k]) * exp(S[q,k])
// Engine: mma.sync.m16n8k16 bf16 (sm_80+ ISA; tcgen05 rejected at the
// harness's compute_100 PTX target). Precision: hi/lo bf16 split, 3-pass.
// R5: chunk depth 32, double-buffer = 82KB smem -> 2 CTAs/SM (was 1).
#define BH 32
#define CD 128
#define LL 2048

// ---------------- scratch (device globals; allocation is banned) ----------
__device__ __nv_bfloat16 g_Qh[(size_t)BH * LL * CD];  // [bh][q][c]
__device__ __nv_bfloat16 g_Ql[(size_t)BH * LL * CD];
__device__ __nv_bfloat16 g_Kh[(size_t)BH * LL * CD];  // [bh][k][c]
__device__ __nv_bfloat16 g_Kl[(size_t)BH * LL * CD];
__device__ __nv_bfloat16 g_Vh[(size_t)BH * CD * LL];  // [bh][c][k] (V*rinv)
__device__ __nv_bfloat16 g_Vl[(size_t)BH * CD * LL];
__device__ __nv_bfloat16 g_Eh[(size_t)BH * LL * LL];  // [bh][q][k]
__device__ __nv_bfloat16 g_El[(size_t)BH * LL * LL];
__device__ float         g_r[BH * LL];

// ---------------- smem geometry -------------------------------------------
#define TSTR   80                 // bytes/row in 32-col bf16 tiles (odd 16B)
#define TILE_B (128 * TSTR)       // 10240
#define BUF_B  (4 * TILE_B)       // 40960 : Ah | Al | Bh | Bl
#define OFF_AH 0
#define OFF_AL TILE_B
#define OFF_BH (2 * TILE_B)
#define OFF_BL (3 * TILE_B)
#define OFF_CS (2 * BUF_B)        // 81920
#define SMEM_SZ (OFF_CS + 512)    // 82432 -> 2 CTAs/SM
#define ESTR   272                // staging row stride bytes (68 u32, odd 16B)

// ---------------- ptx helpers ---------------------------------------------
__device__ __forceinline__ uint32_t smem_u32(const void* p) {
    uint32_t a;
    asm("{ .reg .u64 t; cvta.to.shared.u64 t, %1; cvt.u32.u64 %0, t; }"
        : "=r"(a) : "l"(p));
    return a;
}
__device__ __forceinline__ void cpa(uint32_t d, const void* s) {
    asm volatile("cp.async.cg.shared.global [%0], [%1], 16;"
                 :: "r"(d), "l"(__cvta_generic_to_global(s)));
}
#define CP_COMMIT() asm volatile("cp.async.commit_group;" ::: "memory")
#define CP_WAIT(n)  asm volatile("cp.async.wait_group %0;" :: "n"(n) : "memory")

__device__ __forceinline__ void ldsm4(uint32_t* r, uint32_t a) {
    asm volatile("ldmatrix.sync.aligned.m8n8.x4.shared.b16 {%0,%1,%2,%3}, [%4];"
                 : "=r"(r[0]), "=r"(r[1]), "=r"(r[2]), "=r"(r[3]) : "r"(a));
}
__device__ __forceinline__ void ldsm2(uint32_t* r, uint32_t a) {
    asm volatile("ldmatrix.sync.aligned.m8n8.x2.shared.b16 {%0,%1}, [%2];"
                 : "=r"(r[0]), "=r"(r[1]) : "r"(a));
}
__device__ __forceinline__ void mma16816(float* d, const uint32_t* a, const uint32_t* b) {
    asm volatile("mma.sync.aligned.m16n8k16.row.col.f32.bf16.bf16.f32 "
                 "{%0,%1,%2,%3}, {%4,%5,%6,%7}, {%8,%9}, {%0,%1,%2,%3};"
                 : "+f"(d[0]), "+f"(d[1]), "+f"(d[2]), "+f"(d[3])
                 : "r"(a[0]), "r"(a[1]), "r"(a[2]), "r"(a[3]),
                   "r"(b[0]), "r"(b[1]));
}

// load one 4-tile k-chunk (Ah,Al,Bh,Bl: 128 rows x 32 bf16 each) via cp.async
__device__ __forceinline__ void load_chunk(
    uint32_t buf, const __nv_bfloat16* ah, const __nv_bfloat16* al,
    const __nv_bfloat16* bh, const __nv_bfloat16* bl,
    int strideA, int strideB, int tid)
{
#pragma unroll
    for (int r = 0; r < 2; r++) {
        int idx = tid + 256 * r;       // 0..511
        int row = idx >> 2, seg = idx & 3;
        uint32_t d = buf + row * TSTR + seg * 16;
        size_t sa = (size_t)row * strideA + seg * 8;
        size_t sb = (size_t)row * strideB + seg * 8;
        cpa(d + OFF_AH, ah + sa);
        cpa(d + OFF_AL, al + sa);
        cpa(d + OFF_BH, bh + sb);
        cpa(d + OFF_BL, bl + sb);
    }
}

// one 32-deep k-chunk of 3-pass split mma: acc += Ah*Bh + Ah*Bl + Al*Bh
__device__ __forceinline__ void mma_chunk(
    float acc[4][4][4], uint32_t buf, int wm, int wn, int lane)
{
    uint32_t a_base = buf + (uint32_t)(wm * 64 + (lane & 15)) * TSTR + ((lane >> 4) << 4);
    uint32_t b_base = buf + (uint32_t)(wn * 32 + (lane & 7)) * TSTR + (((lane >> 3) & 1) << 4);
#pragma unroll
    for (int ks = 0; ks < 2; ks++) {
        uint32_t ah[4][4], al[4][4], bhf[4][2], blf[4][2];
#pragma unroll
        for (int i = 0; i < 4; i++) {
            ldsm4(ah[i], a_base + OFF_AH + i * 16 * TSTR + ks * 32);
            ldsm4(al[i], a_base + OFF_AL + i * 16 * TSTR + ks * 32);
        }
#pragma unroll
        for (int j = 0; j < 4; j++) {
            ldsm2(bhf[j], b_base + OFF_BH + j * 8 * TSTR + ks * 32);
            ldsm2(blf[j], b_base + OFF_BL + j * 8 * TSTR + ks * 32);
        }
#pragma unroll
        for (int i = 0; i < 4; i++)
#pragma unroll
            for (int j = 0; j < 4; j++) {
                mma16816(acc[i][j], ah[i], bhf[j]);
                mma16816(acc[i][j], ah[i], blf[j]);
                mma16816(acc[i][j], al[i], bhf[j]);
            }
    }
}

// ---------------------------------------------------------------------------
// small kernels
// ---------------------------------------------------------------------------
__global__ void zero_r_kernel() {
    int i = blockIdx.x * blockDim.x + threadIdx.x;
    if (i < BH * LL) g_r[i] = 0.0f;
}
__global__ void rinv_kernel() {
    int i = blockIdx.x * blockDim.x + threadIdx.x;
    if (i < BH * LL) g_r[i] = 1.0f / g_r[i];
}

// transpose+split: X [bh][c][l] f32 -> (Xh,Xl) [bh][l][c] bf16. sel 0=Q 1=K
__global__ void splitT_kernel(const float* __restrict__ X, int sel) {
    __shared__ float tbuf[32][33];
    int bh = blockIdx.z, c0 = blockIdx.y * 32, l0 = blockIdx.x * 32;
    int tx = threadIdx.x, ty = threadIdx.y;
    const float* Xb = X + ((size_t)bh * CD + c0) * LL + l0;
#pragma unroll
    for (int i = 0; i < 4; i++)
        tbuf[ty + 8 * i][tx] = Xb[(size_t)(ty + 8 * i) * LL + tx];
    __syncthreads();
    __nv_bfloat16* Dh = (sel ? g_Kh : g_Qh) + ((size_t)bh * LL + l0) * CD + c0;
    __nv_bfloat16* Dl = (sel ? g_Kl : g_Ql) + ((size_t)bh * LL + l0) * CD + c0;
#pragma unroll
    for (int i = 0; i < 4; i++) {
        float v = tbuf[tx][ty + 8 * i];
        __nv_bfloat16 h = __float2bfloat16(v);
        Dh[(size_t)(ty + 8 * i) * CD + tx] = h;
        Dl[(size_t)(ty + 8 * i) * CD + tx] = __float2bfloat16(v - __bfloat162float(h));
    }
}

// Vr = V * rinv -> bf16 hi/lo, layout unchanged [bh][c][k]
__global__ void vprep_kernel(const float* __restrict__ V) {
    const size_t N = (size_t)BH * CD * LL;
    for (size_t i = (size_t)blockIdx.x * blockDim.x + threadIdx.x; i < N;
         i += (size_t)gridDim.x * blockDim.x) {
        int k = (int)(i & (LL - 1));
        int bh = (int)(i / ((size_t)CD * LL));
        float v = V[i] * g_r[bh * LL + k];
        __nv_bfloat16 h = __float2bfloat16(v);
        g_Vh[i] = h;
        g_Vl[i] = __float2bfloat16(v - __bfloat162float(h));
    }
}

// ---------------------------------------------------------------------------
// GEMM1: S tile [128q x 128k] over c=128 (4 chunks of 32), exp epilogue,
//        colsum->g_r, split-store Eh/El via coalescing staging.
// grid (16 qt, 16 kt, 32 bh), 256 threads, 2 CTAs/SM
// ---------------------------------------------------------------------------
__global__ __launch_bounds__(256, 2) void gemm1_kernel() {
    extern __shared__ char sm[];
    const uint32_t sb = smem_u32(sm);
    const int tid = threadIdx.x, wid = tid >> 5, lane = tid & 31;
    const int wm = wid & 1, wn = wid >> 1;
    const int q0 = blockIdx.x * 128, k0 = blockIdx.y * 128, bh = blockIdx.z;

    float* cs = (float*)(sm + OFF_CS);
    if (tid < 128) cs[tid] = 0.0f;

    const __nv_bfloat16* Qh = g_Qh + ((size_t)bh * LL + q0) * CD;
    const __nv_bfloat16* Ql = g_Ql + ((size_t)bh * LL + q0) * CD;
    const __nv_bfloat16* Kh = g_Kh + ((size_t)bh * LL + k0) * CD;
    const __nv_bfloat16* Kl = g_Kl + ((size_t)bh * LL + k0) * CD;

    load_chunk(sb, Qh, Ql, Kh, Kl, CD, CD, tid);
    CP_COMMIT();
    load_chunk(sb + BUF_B, Qh + 32, Ql + 32, Kh + 32, Kl + 32, CD, CD, tid);
    CP_COMMIT();

    float acc[4][4][4];
#pragma unroll
    for (int i = 0; i < 4; i++)
#pragma unroll
        for (int j = 0; j < 4; j++)
#pragma unroll
            for (int v = 0; v < 4; v++) acc[i][j][v] = 0.0f;

#pragma unroll 1
    for (int ck = 0; ck < 4; ck++) {
        if (ck == 3) { CP_WAIT(0); } else { CP_WAIT(1); }
        __syncthreads();
        mma_chunk(acc, sb + (ck & 1) * BUF_B, wm, wn, lane);
        __syncthreads();
        if (ck + 2 < 4) {
            int off = (ck + 2) * 32;
            load_chunk(sb + (ck & 1) * BUF_B, Qh + off, Ql + off,
                       Kh + off, Kl + off, CD, CD, tid);
            CP_COMMIT();
        }
    }

    // exp in place + column sums
#pragma unroll
    for (int i = 0; i < 4; i++)
#pragma unroll
        for (int j = 0; j < 4; j++)
#pragma unroll
            for (int v = 0; v < 4; v++) acc[i][j][v] = __expf(acc[i][j][v]);

#pragma unroll
    for (int j = 0; j < 4; j++) {
        float p0 = 0.0f, p1 = 0.0f;
#pragma unroll
        for (int i = 0; i < 4; i++) {
            p0 += acc[i][j][0] + acc[i][j][2];
            p1 += acc[i][j][1] + acc[i][j][3];
        }
        p0 += __shfl_xor_sync(0xffffffffu, p0, 4);
        p1 += __shfl_xor_sync(0xffffffffu, p1, 4);
        p0 += __shfl_xor_sync(0xffffffffu, p0, 8);
        p1 += __shfl_xor_sync(0xffffffffu, p1, 8);
        p0 += __shfl_xor_sync(0xffffffffu, p0, 16);
        p1 += __shfl_xor_sync(0xffffffffu, p1, 16);
        if ((lane >> 2) == 0) {
            int c = wn * 32 + j * 8 + (lane & 3) * 2;
            atomicAdd(&cs[c], p0);
            atomicAdd(&cs[c + 1], p1);
        }
    }

    // stage hi/lo bf16x2 tiles (conflict-free 272B-row layout, reuses buffers)
    uint32_t* stH = (uint32_t*)(sm);
    uint32_t* stL = (uint32_t*)(sm + 128 * ESTR);
#pragma unroll
    for (int i = 0; i < 4; i++)
#pragma unroll
        for (int j = 0; j < 4; j++) {
            int r  = wm * 64 + i * 16 + (lane >> 2);
            int cu = wn * 16 + j * 4 + (lane & 3);
            float a0 = acc[i][j][0], a1 = acc[i][j][1];
            float a2 = acc[i][j][2], a3 = acc[i][j][3];
            __nv_bfloat16 h0 = __float2bfloat16(a0), h1 = __float2bfloat16(a1);
            __nv_bfloat16 h2 = __float2bfloat16(a2), h3 = __float2bfloat16(a3);
            stH[r * 68 + cu] = (uint32_t)__bfloat16_as_ushort(h0) |
                               ((uint32_t)__bfloat16_as_ushort(h1) << 16);
            stH[(r + 8) * 68 + cu] = (uint32_t)__bfloat16_as_ushort(h2) |
                                     ((uint32_t)__bfloat16_as_ushort(h3) << 16);
            __nv_bfloat16 l0 = __float2bfloat16(a0 - __bfloat162float(h0));
            __nv_bfloat16 l1 = __float2bfloat16(a1 - __bfloat162float(h1));
            __nv_bfloat16 l2 = __float2bfloat16(a2 - __bfloat162float(h2));
            __nv_bfloat16 l3 = __float2bfloat16(a3 - __bfloat162float(h3));
            stL[r * 68 + cu] = (uint32_t)__bfloat16_as_ushort(l0) |
                               ((uint32_t)__bfloat16_as_ushort(l1) << 16);
            stL[(r + 8) * 68 + cu] = (uint32_t)__bfloat16_as_ushort(l2) |
                                     ((uint32_t)__bfloat16_as_ushort(l3) << 16);
        }
    __syncthreads();

    if (tid < 128) atomicAdd(&g_r[bh * LL + k0 + tid], cs[tid]);

    __nv_bfloat16* EhD = g_Eh + ((size_t)bh * LL + q0) * LL + k0;
    __nv_bfloat16* ElD = g_El + ((size_t)bh * LL + q0) * LL + k0;
#pragma unroll
    for (int r8 = 0; r8 < 8; r8++) {
        int idx = tid + 256 * r8;        // 0..2047
        int row = idx >> 4, seg = idx & 15;
        *(uint4*)(EhD + (size_t)row * LL + seg * 8) =
            *(const uint4*)((const char*)sm + row * ESTR + seg * 16);
        *(uint4*)(ElD + (size_t)row * LL + seg * 8) =
            *(const uint4*)((const char*)sm + 128 * ESTR + row * ESTR + seg * 16);
    }
}

// ---------------------------------------------------------------------------
// GEMM2: O[c,q] = sum_k Vr[c,k]*E[q,k]; 64 double-buffered k-chunks of 32.
// grid (16 qt, 32 bh), 256 threads, 2 CTAs/SM
// ---------------------------------------------------------------------------
__global__ __launch_bounds__(256, 2) void gemm2_kernel(float* __restrict__ Out) {
    extern __shared__ char sm[];
    const uint32_t sb = smem_u32(sm);
    const int tid = threadIdx.x, wid = tid >> 5, lane = tid & 31;
    const int wm = wid & 1, wn = wid >> 1;
    const int q0 = blockIdx.x * 128, bh = blockIdx.y;

    const __nv_bfloat16* Vh = g_Vh + (size_t)bh * CD * LL;
    const __nv_bfloat16* Vl = g_Vl + (size_t)bh * CD * LL;
    const __nv_bfloat16* Eh = g_Eh + ((size_t)bh * LL + q0) * LL;
    const __nv_bfloat16* El = g_El + ((size_t)bh * LL + q0) * LL;

    load_chunk(sb, Vh, Vl, Eh, El, LL, LL, tid);
    CP_COMMIT();
    load_chunk(sb + BUF_B, Vh + 32, Vl + 32, Eh + 32, El + 32, LL, LL, tid);
    CP_COMMIT();

    float acc[4][4][4];
#pragma unroll
    for (int i = 0; i < 4; i++)
#pragma unroll
        for (int j = 0; j < 4; j++)
#pragma unroll
            for (int v = 0; v < 4; v++) acc[i][j][v] = 0.0f;

#pragma unroll 1
    for (int ck = 0; ck < 64; ck++) {
        if (ck == 63) { CP_WAIT(0); } else { CP_WAIT(1); }
        __syncthreads();
        mma_chunk(acc, sb + (ck & 1) * BUF_B, wm, wn, lane);
        __syncthreads();
        if (ck + 2 < 64) {
            int off = (ck + 2) * 32;
            load_chunk(sb + (ck & 1) * BUF_B, Vh + off, Vl + off,
                       Eh + off, El + off, LL, LL, tid);
            CP_COMMIT();
        }
    }

    // epilogue: direct f32 stores, Out [bh][c][q]
#pragma unroll
    for (int i = 0; i < 4; i++)
#pragma unroll
        for (int j = 0; j < 4; j++) {
            int r  = wm * 64 + i * 16 + (lane >> 2);
            int qc = q0 + wn * 32 + j * 8 + (lane & 3) * 2;
            float* ob = Out + ((size_t)bh * CD + r) * LL + qc;
            *(float2*)ob = make_float2(acc[i][j][0], acc[i][j][1]);
            *(float2*)(ob + 8 * LL) = make_float2(acc[i][j][2], acc[i][j][3]);
        }
}

// ---------------------------------------------------------------------------
extern "C" void kernel_launch(void* const* d_in, const int* in_sizes, int n_in,
                              void* d_out, int out_size)
{
    const float* q = (const float*)d_in[0];
    const float* k = (const float*)d_in[1];
    const float* v = (const float*)d_in[2];
    float* out = (float*)d_out;

    cudaFuncSetAttribute(gemm1_kernel, cudaFuncAttributeMaxDynamicSharedMemorySize, SMEM_SZ);
    cudaFuncSetAttribute(gemm2_kernel, cudaFuncAttributeMaxDynamicSharedMemorySize, SMEM_SZ);

    zero_r_kernel<<<BH * LL / 256, 256>>>();
    splitT_kernel<<<dim3(LL / 32, CD / 32, BH), dim3(32, 8)>>>(q, 0);
    splitT_kernel<<<dim3(LL / 32, CD / 32, BH), dim3(32, 8)>>>(k, 1);
    gemm1_kernel<<<dim3(16, 16, BH), 256, SMEM_SZ>>>();
    rinv_kernel<<<BH * LL / 256, 256>>>();
    vprep_kernel<<<4096, 256>>>(v);
    gemm2_kernel<<<dim3(16, BH), 256, SMEM_SZ>>>(out);
}

// round 6
// speedup vs baseline: 2.3422x; 1.0263x over previous
#include <cuda_runtime.h>
#include <cuda_bf16.h>
#include <cstdint>

// Problem: q,k,v [B=2,H=16,C=128,L=2048] fp32, L contiguous.
// weights = softmax over the q axis:
//   r[k]   = sum_q exp(S[q,k]),  S = Q^T K
//   O[c,q] = sum_k (V[c,k]/r[k]) * exp(S[q,k])
// Engine: mma.sync.m16n8k16 bf16 (tcgen05 rejected at compute_100 target).
// Precision: hi/lo bf16 split, 3-pass (hh+hl+lh).
// R6: 1 barrier per k-chunk (load-before-mma reorder), B frags via ldsm.x4.
#define BH 32
#define CD 128
#define LL 2048

// ---------------- scratch (device globals; allocation is banned) ----------
__device__ __nv_bfloat16 g_Qh[(size_t)BH * LL * CD];  // [bh][q][c]
__device__ __nv_bfloat16 g_Ql[(size_t)BH * LL * CD];
__device__ __nv_bfloat16 g_Kh[(size_t)BH * LL * CD];  // [bh][k][c]
__device__ __nv_bfloat16 g_Kl[(size_t)BH * LL * CD];
__device__ __nv_bfloat16 g_Vh[(size_t)BH * CD * LL];  // [bh][c][k] (V*rinv)
__device__ __nv_bfloat16 g_Vl[(size_t)BH * CD * LL];
__device__ __nv_bfloat16 g_Eh[(size_t)BH * LL * LL];  // [bh][q][k]
__device__ __nv_bfloat16 g_El[(size_t)BH * LL * LL];
__device__ float         g_r[BH * LL];

// ---------------- smem geometry -------------------------------------------
#define TSTR   80                 // bytes/row in 32-col bf16 tiles (odd 16B)
#define TILE_B (128 * TSTR)       // 10240
#define BUF_B  (4 * TILE_B)       // 40960 : Ah | Al | Bh | Bl
#define OFF_AH 0
#define OFF_AL TILE_B
#define OFF_BH (2 * TILE_B)
#define OFF_BL (3 * TILE_B)
#define OFF_CS (2 * BUF_B)        // 81920
#define SMEM_SZ (OFF_CS + 512)    // 82432 -> 2 CTAs/SM
#define ESTR   272                // staging row stride bytes (68 u32, odd 16B)

// ---------------- ptx helpers ---------------------------------------------
__device__ __forceinline__ uint32_t smem_u32(const void* p) {
    uint32_t a;
    asm("{ .reg .u64 t; cvta.to.shared.u64 t, %1; cvt.u32.u64 %0, t; }"
        : "=r"(a) : "l"(p));
    return a;
}
__device__ __forceinline__ void cpa(uint32_t d, const void* s) {
    asm volatile("cp.async.cg.shared.global [%0], [%1], 16;"
                 :: "r"(d), "l"(__cvta_generic_to_global(s)));
}
#define CP_COMMIT() asm volatile("cp.async.commit_group;" ::: "memory")
#define CP_WAIT(n)  asm volatile("cp.async.wait_group %0;" :: "n"(n) : "memory")

__device__ __forceinline__ void ldsm4(uint32_t* r, uint32_t a) {
    asm volatile("ldmatrix.sync.aligned.m8n8.x4.shared.b16 {%0,%1,%2,%3}, [%4];"
                 : "=r"(r[0]), "=r"(r[1]), "=r"(r[2]), "=r"(r[3]) : "r"(a));
}
__device__ __forceinline__ void mma16816(float* d, const uint32_t* a, const uint32_t* b) {
    asm volatile("mma.sync.aligned.m16n8k16.row.col.f32.bf16.bf16.f32 "
                 "{%0,%1,%2,%3}, {%4,%5,%6,%7}, {%8,%9}, {%0,%1,%2,%3};"
                 : "+f"(d[0]), "+f"(d[1]), "+f"(d[2]), "+f"(d[3])
                 : "r"(a[0]), "r"(a[1]), "r"(a[2]), "r"(a[3]),
                   "r"(b[0]), "r"(b[1]));
}

// load one 4-tile k-chunk (Ah,Al,Bh,Bl: 128 rows x 32 bf16 each) via cp.async
__device__ __forceinline__ void load_chunk(
    uint32_t buf, const __nv_bfloat16* ah, const __nv_bfloat16* al,
    const __nv_bfloat16* bh, const __nv_bfloat16* bl,
    int strideA, int strideB, int tid)
{
#pragma unroll
    for (int r = 0; r < 2; r++) {
        int idx = tid + 256 * r;       // 0..511
        int row = idx >> 2, seg = idx & 3;
        uint32_t d = buf + row * TSTR + seg * 16;
        size_t sa = (size_t)row * strideA + seg * 8;
        size_t sb = (size_t)row * strideB + seg * 8;
        cpa(d + OFF_AH, ah + sa);
        cpa(d + OFF_AL, al + sa);
        cpa(d + OFF_BH, bh + sb);
        cpa(d + OFF_BL, bl + sb);
    }
}

// one 32-deep k-chunk of 3-pass split mma: acc += Ah*Bh + Ah*Bl + Al*Bh
// B fragments for two adjacent 8-col blocks come from one ldsm.x4
// (lanes 0-15 -> n block +0, lanes 16-31 -> n block +8).
__device__ __forceinline__ void mma_chunk(
    float acc[4][4][4], uint32_t buf, int wm, int wn, int lane)
{
    uint32_t a_base = buf + (uint32_t)(wm * 64 + (lane & 15)) * TSTR + ((lane >> 4) << 4);
    uint32_t b_base = buf + (uint32_t)(wn * 32 + ((lane >> 4) << 3) + (lane & 7)) * TSTR
                    + (((lane >> 3) & 1) << 4);
#pragma unroll
    for (int ks = 0; ks < 2; ks++) {
        uint32_t ah[4][4], al[4][4], bhf[4][2], blf[4][2];
#pragma unroll
        for (int i = 0; i < 4; i++) {
            ldsm4(ah[i], a_base + OFF_AH + i * 16 * TSTR + ks * 32);
            ldsm4(al[i], a_base + OFF_AL + i * 16 * TSTR + ks * 32);
        }
#pragma unroll
        for (int jj = 0; jj < 2; jj++) {
            uint32_t t[4];
            ldsm4(t, b_base + OFF_BH + jj * 16 * TSTR + ks * 32);
            bhf[2 * jj][0] = t[0]; bhf[2 * jj][1] = t[1];
            bhf[2 * jj + 1][0] = t[2]; bhf[2 * jj + 1][1] = t[3];
            ldsm4(t, b_base + OFF_BL + jj * 16 * TSTR + ks * 32);
            blf[2 * jj][0] = t[0]; blf[2 * jj][1] = t[1];
            blf[2 * jj + 1][0] = t[2]; blf[2 * jj + 1][1] = t[3];
        }
#pragma unroll
        for (int i = 0; i < 4; i++)
#pragma unroll
            for (int j = 0; j < 4; j++) {
                mma16816(acc[i][j], ah[i], bhf[j]);
                mma16816(acc[i][j], ah[i], blf[j]);
                mma16816(acc[i][j], al[i], bhf[j]);
            }
    }
}

// ---------------------------------------------------------------------------
// small kernels
// ---------------------------------------------------------------------------
__global__ void zero_r_kernel() {
    int i = blockIdx.x * blockDim.x + threadIdx.x;
    if (i < BH * LL) g_r[i] = 0.0f;
}
__global__ void rinv_kernel() {
    int i = blockIdx.x * blockDim.x + threadIdx.x;
    if (i < BH * LL) g_r[i] = 1.0f / g_r[i];
}

// transpose+split: X [bh][c][l] f32 -> (Xh,Xl) [bh][l][c] bf16. sel 0=Q 1=K
__global__ void splitT_kernel(const float* __restrict__ X, int sel) {
    __shared__ float tbuf[32][33];
    int bh = blockIdx.z, c0 = blockIdx.y * 32, l0 = blockIdx.x * 32;
    int tx = threadIdx.x, ty = threadIdx.y;
    const float* Xb = X + ((size_t)bh * CD + c0) * LL + l0;
#pragma unroll
    for (int i = 0; i < 4; i++)
        tbuf[ty + 8 * i][tx] = Xb[(size_t)(ty + 8 * i) * LL + tx];
    __syncthreads();
    __nv_bfloat16* Dh = (sel ? g_Kh : g_Qh) + ((size_t)bh * LL + l0) * CD + c0;
    __nv_bfloat16* Dl = (sel ? g_Kl : g_Ql) + ((size_t)bh * LL + l0) * CD + c0;
#pragma unroll
    for (int i = 0; i < 4; i++) {
        float v = tbuf[tx][ty + 8 * i];
        __nv_bfloat16 h = __float2bfloat16(v);
        Dh[(size_t)(ty + 8 * i) * CD + tx] = h;
        Dl[(size_t)(ty + 8 * i) * CD + tx] = __float2bfloat16(v - __bfloat162float(h));
    }
}

// Vr = V * rinv -> bf16 hi/lo, layout unchanged [bh][c][k]
__global__ void vprep_kernel(const float* __restrict__ V) {
    const size_t N = (size_t)BH * CD * LL;
    for (size_t i = (size_t)blockIdx.x * blockDim.x + threadIdx.x; i < N;
         i += (size_t)gridDim.x * blockDim.x) {
        int k = (int)(i & (LL - 1));
        int bh = (int)(i / ((size_t)CD * LL));
        float v = V[i] * g_r[bh * LL + k];
        __nv_bfloat16 h = __float2bfloat16(v);
        g_Vh[i] = h;
        g_Vl[i] = __float2bfloat16(v - __bfloat162float(h));
    }
}

// ---------------------------------------------------------------------------
// GEMM1: S tile [128q x 128k] over c=128 (4 chunks of 32), exp epilogue,
//        colsum->g_r, split-store Eh/El via coalescing staging.
// grid (16 qt, 16 kt, 32 bh), 256 threads, 2 CTAs/SM
// ---------------------------------------------------------------------------
__global__ __launch_bounds__(256, 2) void gemm1_kernel() {
    extern __shared__ char sm[];
    const uint32_t sb = smem_u32(sm);
    const int tid = threadIdx.x, wid = tid >> 5, lane = tid & 31;
    const int wm = wid & 1, wn = wid >> 1;
    const int q0 = blockIdx.x * 128, k0 = blockIdx.y * 128, bh = blockIdx.z;

    float* cs = (float*)(sm + OFF_CS);
    if (tid < 128) cs[tid] = 0.0f;

    const __nv_bfloat16* Qh = g_Qh + ((size_t)bh * LL + q0) * CD;
    const __nv_bfloat16* Ql = g_Ql + ((size_t)bh * LL + q0) * CD;
    const __nv_bfloat16* Kh = g_Kh + ((size_t)bh * LL + k0) * CD;
    const __nv_bfloat16* Kl = g_Kl + ((size_t)bh * LL + k0) * CD;

    load_chunk(sb, Qh, Ql, Kh, Kl, CD, CD, tid);
    CP_COMMIT();

    float acc[4][4][4];
#pragma unroll
    for (int i = 0; i < 4; i++)
#pragma unroll
        for (int j = 0; j < 4; j++)
#pragma unroll
            for (int v = 0; v < 4; v++) acc[i][j][v] = 0.0f;

    // 1 barrier per chunk: wait(load ck) ; sync (mma ck-1 done everywhere) ;
    // issue load ck+1 into the buffer mma ck-1 just vacated ; mma ck.
#pragma unroll 1
    for (int ck = 0; ck < 4; ck++) {
        CP_WAIT(0);
        __syncthreads();
        if (ck + 1 < 4) {
            int off = (ck + 1) * 32;
            load_chunk(sb + ((ck + 1) & 1) * BUF_B, Qh + off, Ql + off,
                       Kh + off, Kl + off, CD, CD, tid);
            CP_COMMIT();
        }
        mma_chunk(acc, sb + (ck & 1) * BUF_B, wm, wn, lane);
    }
    __syncthreads();   // all warps done with buffers -> staging may reuse smem

    // exp in place + column sums
#pragma unroll
    for (int i = 0; i < 4; i++)
#pragma unroll
        for (int j = 0; j < 4; j++)
#pragma unroll
            for (int v = 0; v < 4; v++) acc[i][j][v] = __expf(acc[i][j][v]);

#pragma unroll
    for (int j = 0; j < 4; j++) {
        float p0 = 0.0f, p1 = 0.0f;
#pragma unroll
        for (int i = 0; i < 4; i++) {
            p0 += acc[i][j][0] + acc[i][j][2];
            p1 += acc[i][j][1] + acc[i][j][3];
        }
        p0 += __shfl_xor_sync(0xffffffffu, p0, 4);
        p1 += __shfl_xor_sync(0xffffffffu, p1, 4);
        p0 += __shfl_xor_sync(0xffffffffu, p0, 8);
        p1 += __shfl_xor_sync(0xffffffffu, p1, 8);
        p0 += __shfl_xor_sync(0xffffffffu, p0, 16);
        p1 += __shfl_xor_sync(0xffffffffu, p1, 16);
        if ((lane >> 2) == 0) {
            int c = wn * 32 + j * 8 + (lane & 3) * 2;
            atomicAdd(&cs[c], p0);
            atomicAdd(&cs[c + 1], p1);
        }
    }

    // stage hi/lo bf16x2 tiles (conflict-free 272B-row layout, reuses buffers)
    uint32_t* stH = (uint32_t*)(sm);
    uint32_t* stL = (uint32_t*)(sm + 128 * ESTR);
#pragma unroll
    for (int i = 0; i < 4; i++)
#pragma unroll
        for (int j = 0; j < 4; j++) {
            int r  = wm * 64 + i * 16 + (lane >> 2);
            int cu = wn * 16 + j * 4 + (lane & 3);
            float a0 = acc[i][j][0], a1 = acc[i][j][1];
            float a2 = acc[i][j][2], a3 = acc[i][j][3];
            __nv_bfloat16 h0 = __float2bfloat16(a0), h1 = __float2bfloat16(a1);
            __nv_bfloat16 h2 = __float2bfloat16(a2), h3 = __float2bfloat16(a3);
            stH[r * 68 + cu] = (uint32_t)__bfloat16_as_ushort(h0) |
                               ((uint32_t)__bfloat16_as_ushort(h1) << 16);
            stH[(r + 8) * 68 + cu] = (uint32_t)__bfloat16_as_ushort(h2) |
                                     ((uint32_t)__bfloat16_as_ushort(h3) << 16);
            __nv_bfloat16 l0 = __float2bfloat16(a0 - __bfloat162float(h0));
            __nv_bfloat16 l1 = __float2bfloat16(a1 - __bfloat162float(h1));
            __nv_bfloat16 l2 = __float2bfloat16(a2 - __bfloat162float(h2));
            __nv_bfloat16 l3 = __float2bfloat16(a3 - __bfloat162float(h3));
            stL[r * 68 + cu] = (uint32_t)__bfloat16_as_ushort(l0) |
                               ((uint32_t)__bfloat16_as_ushort(l1) << 16);
            stL[(r + 8) * 68 + cu] = (uint32_t)__bfloat16_as_ushort(l2) |
                                     ((uint32_t)__bfloat16_as_ushort(l3) << 16);
        }
    __syncthreads();

    if (tid < 128) atomicAdd(&g_r[bh * LL + k0 + tid], cs[tid]);

    __nv_bfloat16* EhD = g_Eh + ((size_t)bh * LL + q0) * LL + k0;
    __nv_bfloat16* ElD = g_El + ((size_t)bh * LL + q0) * LL + k0;
#pragma unroll
    for (int r8 = 0; r8 < 8; r8++) {
        int idx = tid + 256 * r8;        // 0..2047
        int row = idx >> 4, seg = idx & 15;
        *(uint4*)(EhD + (size_t)row * LL + seg * 8) =
            *(const uint4*)((const char*)sm + row * ESTR + seg * 16);
        *(uint4*)(ElD + (size_t)row * LL + seg * 8) =
            *(const uint4*)((const char*)sm + 128 * ESTR + row * ESTR + seg * 16);
    }
}

// ---------------------------------------------------------------------------
// GEMM2: O[c,q] = sum_k Vr[c,k]*E[q,k]; 64 k-chunks of 32, double-buffered,
//        one barrier per chunk.
// grid (16 qt, 32 bh), 256 threads, 2 CTAs/SM
// ---------------------------------------------------------------------------
__global__ __launch_bounds__(256, 2) void gemm2_kernel(float* __restrict__ Out) {
    extern __shared__ char sm[];
    const uint32_t sb = smem_u32(sm);
    const int tid = threadIdx.x, wid = tid >> 5, lane = tid & 31;
    const int wm = wid & 1, wn = wid >> 1;
    const int q0 = blockIdx.x * 128, bh = blockIdx.y;

    const __nv_bfloat16* Vh = g_Vh + (size_t)bh * CD * LL;
    const __nv_bfloat16* Vl = g_Vl + (size_t)bh * CD * LL;
    const __nv_bfloat16* Eh = g_Eh + ((size_t)bh * LL + q0) * LL;
    const __nv_bfloat16* El = g_El + ((size_t)bh * LL + q0) * LL;

    load_chunk(sb, Vh, Vl, Eh, El, LL, LL, tid);
    CP_COMMIT();

    float acc[4][4][4];
#pragma unroll
    for (int i = 0; i < 4; i++)
#pragma unroll
        for (int j = 0; j < 4; j++)
#pragma unroll
            for (int v = 0; v < 4; v++) acc[i][j][v] = 0.0f;

#pragma unroll 1
    for (int ck = 0; ck < 64; ck++) {
        CP_WAIT(0);
        __syncthreads();
        if (ck + 1 < 64) {
            int off = (ck + 1) * 32;
            load_chunk(sb + ((ck + 1) & 1) * BUF_B, Vh + off, Vl + off,
                       Eh + off, El + off, LL, LL, tid);
            CP_COMMIT();
        }
        mma_chunk(acc, sb + (ck & 1) * BUF_B, wm, wn, lane);
    }

    // epilogue: direct f32 stores, Out [bh][c][q]
#pragma unroll
    for (int i = 0; i < 4; i++)
#pragma unroll
        for (int j = 0; j < 4; j++) {
            int r  = wm * 64 + i * 16 + (lane >> 2);
            int qc = q0 + wn * 32 + j * 8 + (lane & 3) * 2;
            float* ob = Out + ((size_t)bh * CD + r) * LL + qc;
            *(float2*)ob = make_float2(acc[i][j][0], acc[i][j][1]);
            *(float2*)(ob + 8 * LL) = make_float2(acc[i][j][2], acc[i][j][3]);
        }
}

// ---------------------------------------------------------------------------
extern "C" void kernel_launch(void* const* d_in, const int* in_sizes, int n_in,
                              void* d_out, int out_size)
{
    const float* q = (const float*)d_in[0];
    const float* k = (const float*)d_in[1];
    const float* v = (const float*)d_in[2];
    float* out = (float*)d_out;

    cudaFuncSetAttribute(gemm1_kernel, cudaFuncAttributeMaxDynamicSharedMemorySize, SMEM_SZ);
    cudaFuncSetAttribute(gemm2_kernel, cudaFuncAttributeMaxDynamicSharedMemorySize, SMEM_SZ);

    zero_r_kernel<<<BH * LL / 256, 256>>>();
    splitT_kernel<<<dim3(LL / 32, CD / 32, BH), dim3(32, 8)>>>(q, 0);
    splitT_kernel<<<dim3(LL / 32, CD / 32, BH), dim3(32, 8)>>>(k, 1);
    gemm1_kernel<<<dim3(16, 16, BH), 256, SMEM_SZ>>>();
    rinv_kernel<<<BH * LL / 256, 256>>>();
    vprep_kernel<<<4096, 256>>>(v);
    gemm2_kernel<<<dim3(16, BH), 256, SMEM_SZ>>>(out);
}